// round 1
// baseline (speedup 1.0000x reference)
#include <cuda_runtime.h>
#include <math.h>

#define NN 50000
#define EE 800000
#define HH 64

// ---- scratch (device globals: no allocation allowed) ----
__device__ float g_P [NN*HH];
__device__ float g_Q [NN*HH];
__device__ float g_Vm[NN*HH];
__device__ float g_Dc[NN*HH];
__device__ float g_h [NN*HH];
__device__ int   g_deg[NN];
__device__ int   g_rowptr[NN+1];
__device__ int   g_wp[NN];
__device__ int   g_ssrc[EE];

// ---------------- CSR build ----------------
__global__ void k_zero_deg() {
    int i = blockIdx.x * blockDim.x + threadIdx.x;
    if (i < NN) g_deg[i] = 0;
}

__global__ void k_hist(const int* __restrict__ dst) {
    int e = blockIdx.x * blockDim.x + threadIdx.x;
    if (e < EE) atomicAdd(&g_deg[dst[e]], 1);
}

// single-block exclusive scan of deg -> rowptr (+ copy to wp)
__global__ void k_scan() {
    const int T = 1024;
    const int ITEMS = (NN + T - 1) / T;   // 49
    __shared__ int sh[T];
    int t = threadIdx.x;
    int base = t * ITEMS;
    int sum = 0;
    for (int j = 0; j < ITEMS; j++) {
        int i = base + j;
        if (i < NN) sum += g_deg[i];
    }
    sh[t] = sum;
    __syncthreads();
    for (int d = 1; d < T; d <<= 1) {
        int v = (t >= d) ? sh[t - d] : 0;
        __syncthreads();
        sh[t] += v;
        __syncthreads();
    }
    int run = sh[t] - sum;   // exclusive prefix
    for (int j = 0; j < ITEMS; j++) {
        int i = base + j;
        if (i < NN) {
            g_rowptr[i] = run;
            g_wp[i] = run;
            run += g_deg[i];
        }
    }
    if (t == 0) g_rowptr[NN] = EE;
}

__global__ void k_scatter(const int* __restrict__ src, const int* __restrict__ dst) {
    int e = blockIdx.x * blockDim.x + threadIdx.x;
    if (e < EE) {
        int p = atomicAdd(&g_wp[dst[e]], 1);
        g_ssrc[p] = src[e];
    }
}

// ---------------- node projections ----------------
// Computes per node:
//   posproj = pos @ Wpos
//   P  = x@Wdst + posproj + b      (alpha_i  + delta-dst part)
//   Q  = x@Wsrc + posproj          (alpha_j  + delta-src part)
//   Vm = x@Wval - posproj          (value    - delta-src part)
//   Dc = posproj + b               (delta-dst part for value)
// Block: 32 lanes (2 channels each, float2) x 8 nodes.
template<int D, bool USE_GH>
__global__ void k_proj(const float* __restrict__ xin, const float* __restrict__ pos,
                       const float* __restrict__ Wsrc, const float* __restrict__ Wdst,
                       const float* __restrict__ Wval, const float* __restrict__ Wpos,
                       const float* __restrict__ bpos) {
    __shared__ float shx[8][D];
    __shared__ float shp[8][3];
    const float* x = USE_GH ? (const float*)g_h : xin;
    int ty = threadIdx.y, lane = threadIdx.x;
    int node = blockIdx.x * 8 + ty;
    if (node < NN) {
        for (int k = lane; k < D; k += 32) shx[ty][k] = x[node * D + k];
        if (lane < 3) shp[ty][lane] = pos[node * 3 + lane];
    }
    __syncthreads();
    if (node >= NN) return;

    int c = 2 * lane;
    float2 aS = make_float2(0.f, 0.f), aD = aS, aV = aS;
#pragma unroll 8
    for (int k = 0; k < D; k++) {
        float xk = shx[ty][k];
        float2 ws = *(const float2*)&Wsrc[k * HH + c];
        float2 wd = *(const float2*)&Wdst[k * HH + c];
        float2 wv = *(const float2*)&Wval[k * HH + c];
        aS.x += xk * ws.x; aS.y += xk * ws.y;
        aD.x += xk * wd.x; aD.y += xk * wd.y;
        aV.x += xk * wv.x; aV.y += xk * wv.y;
    }
    float2 pp = make_float2(0.f, 0.f);
#pragma unroll
    for (int k = 0; k < 3; k++) {
        float pk = shp[ty][k];
        float2 wp = *(const float2*)&Wpos[k * HH + c];
        pp.x += pk * wp.x; pp.y += pk * wp.y;
    }
    float2 b = *(const float2*)&bpos[c];
    int o = node * HH + c;
    *(float2*)&g_P [o] = make_float2(aD.x + pp.x + b.x, aD.y + pp.y + b.y);
    *(float2*)&g_Q [o] = make_float2(aS.x + pp.x,       aS.y + pp.y);
    *(float2*)&g_Vm[o] = make_float2(aV.x - pp.x,       aV.y - pp.y);
    *(float2*)&g_Dc[o] = make_float2(pp.x + b.x,        pp.y + b.y);
}

// ---------------- edge aggregation: one warp per dst node ----------------
// out[i] = relu( sum_e exp(P[i]-Q[src]) * (Vm[src]+Dc[i]) / sum_e exp(P[i]-Q[src]) )
__global__ void k_edge(float* __restrict__ out) {
    int w = (blockIdx.x * blockDim.x + threadIdx.x) >> 5;
    int lane = threadIdx.x & 31;
    if (w >= NN) return;
    int beg = g_rowptr[w], end = g_rowptr[w + 1];
    int o = w * HH + 2 * lane;
    float2 P2 = *(const float2*)&g_P[o];
    float2 D2 = *(const float2*)&g_Dc[o];
    float2 s = make_float2(0.f, 0.f);
    float2 a = make_float2(0.f, 0.f);
    for (int e = beg; e < end; e++) {
        int sn = g_ssrc[e];
        float2 q  = *(const float2*)&g_Q [sn * HH + 2 * lane];
        float2 vm = *(const float2*)&g_Vm[sn * HH + 2 * lane];
        float e0 = __expf(P2.x - q.x);
        float e1 = __expf(P2.y - q.y);
        s.x += e0;               s.y += e1;
        a.x += e0 * (vm.x + D2.x); a.y += e1 * (vm.y + D2.y);
    }
    float2 r;
    if (end > beg) {
        r.x = fmaxf(a.x / s.x, 0.f);
        r.y = fmaxf(a.y / s.y, 0.f);
    } else {
        r = make_float2(0.f, 0.f);
    }
    *(float2*)&out[o] = r;
}

// ---------------- MLP head: one warp per node ----------------
__global__ void k_head(const float* __restrict__ Wfc1, const float* __restrict__ bfc1,
                       const float* __restrict__ Wfc2, const float* __restrict__ bfc2,
                       float* __restrict__ out) {
    int w = (blockIdx.x * blockDim.x + threadIdx.x) >> 5;
    int lane = threadIdx.x & 31;
    if (w >= NN) return;
    float acc = bfc1[lane];
    const float* hr = &g_h[w * HH];
#pragma unroll 8
    for (int k = 0; k < HH; k++) acc += hr[k] * Wfc1[k * 32 + lane];
    acc = fmaxf(acc, 0.f);
    float y = acc * Wfc2[lane];
#pragma unroll
    for (int off = 16; off; off >>= 1) y += __shfl_xor_sync(0xffffffffu, y, off);
    if (lane == 0) out[w] = y + bfc2[0];
}

extern "C" void kernel_launch(void* const* d_in, const int* in_sizes, int n_in,
                              void* d_out, int out_size) {
    const float* x    = (const float*)d_in[0];
    const float* pos  = (const float*)d_in[1];
    const int*   ei   = (const int*)d_in[2];
    // d_in[3] = batch (unused, single graph)
    const float* W1s  = (const float*)d_in[4];
    const float* W1d  = (const float*)d_in[5];
    const float* W1v  = (const float*)d_in[6];
    const float* W1p  = (const float*)d_in[7];
    const float* b1p  = (const float*)d_in[8];
    const float* W2s  = (const float*)d_in[9];
    const float* W2d  = (const float*)d_in[10];
    const float* W2v  = (const float*)d_in[11];
    const float* W2p  = (const float*)d_in[12];
    const float* b2p  = (const float*)d_in[13];
    const float* Wf1  = (const float*)d_in[14];
    const float* bf1  = (const float*)d_in[15];
    const float* Wf2  = (const float*)d_in[16];
    const float* bf2  = (const float*)d_in[17];
    float* out = (float*)d_out;

    const int* src = ei;
    const int* dst = ei + EE;

    dim3 projBlk(32, 8);
    int projGrid = (NN + 7) / 8;            // 6250
    int nodeWarpGrid = (NN * 32 + 255) / 256; // warp per node, 256 thr/blk
    int edgeGrid = (EE + 255) / 256;        // 3125

    // CSR build (per-call; graph-capturable, deterministic work)
    k_zero_deg<<<(NN + 255) / 256, 256>>>();
    k_hist<<<edgeGrid, 256>>>(dst);
    k_scan<<<1, 1024>>>();
    k_scatter<<<edgeGrid, 256>>>(src, dst);

    // conv1 (in=3)
    k_proj<3, false><<<projGrid, projBlk>>>(x, pos, W1s, W1d, W1v, W1p, b1p);
    float* hdev;
    cudaGetSymbolAddress((void**)&hdev, g_h);
    k_edge<<<nodeWarpGrid, 256>>>(hdev);

    // conv2 (in=H, reads g_h internally)
    k_proj<HH, true><<<projGrid, projBlk>>>(nullptr, pos, W2s, W2d, W2v, W2p, b2p);
    k_edge<<<nodeWarpGrid, 256>>>(hdev);

    // MLP head
    k_head<<<nodeWarpGrid, 256>>>(Wf1, bf1, Wf2, bf2, out);
}

// round 2
// speedup vs baseline: 1.2911x; 1.2911x over previous
#include <cuda_runtime.h>
#include <math.h>

#define NN 50000
#define EE 800000
#define HH 64

// ---- scratch (device globals) ----
__device__ float4 g_T [NN * 32];   // per node, per lane: (eq0, eq1, ev0, ev1)
__device__ float2 g_Dc[NN * 32];   // per node, per lane-pair: posproj + b
__device__ float  g_h [NN * HH];   // conv output / next-layer input
__device__ int    g_deg[NN];
__device__ int    g_rowptr[NN + 1];
__device__ int    g_wp[NN];
__device__ int    g_ssrc[EE];

// ---- packed f32x2 helpers (Blackwell) ----
typedef unsigned long long ull;
__device__ __forceinline__ ull PK(float x, float y) {
    float2 f = make_float2(x, y);
    return *(ull*)&f;
}
__device__ __forceinline__ ull ADD2(ull a, ull b) {
    ull r; asm("add.rn.f32x2 %0, %1, %2;" : "=l"(r) : "l"(a), "l"(b)); return r;
}
__device__ __forceinline__ ull FMA2(ull a, ull b, ull c) {
    ull r; asm("fma.rn.f32x2 %0, %1, %2, %3;" : "=l"(r) : "l"(a), "l"(b), "l"(c)); return r;
}

// ---------------- CSR build ----------------
__global__ void k_hist(const int* __restrict__ dst) {
    int e = blockIdx.x * blockDim.x + threadIdx.x;
    if (e < EE) atomicAdd(&g_deg[dst[e]], 1);
}

__global__ void k_scan() {
    const int T = 1024;
    const int ITEMS = (NN + T - 1) / T;
    __shared__ int sh[T];
    int t = threadIdx.x;
    int base = t * ITEMS;
    int sum = 0;
    for (int j = 0; j < ITEMS; j++) {
        int i = base + j;
        if (i < NN) sum += g_deg[i];
    }
    sh[t] = sum;
    __syncthreads();
    for (int d = 1; d < T; d <<= 1) {
        int v = (t >= d) ? sh[t - d] : 0;
        __syncthreads();
        sh[t] += v;
        __syncthreads();
    }
    int run = sh[t] - sum;
    for (int j = 0; j < ITEMS; j++) {
        int i = base + j;
        if (i < NN) {
            g_rowptr[i] = run;
            g_wp[i] = run;
            run += g_deg[i];
        }
    }
    if (t == 0) g_rowptr[NN] = EE;
}

__global__ void k_scatter(const int* __restrict__ src, const int* __restrict__ dst) {
    int e = blockIdx.x * blockDim.x + threadIdx.x;
    if (e < EE) {
        int p = atomicAdd(&g_wp[dst[e]], 1);
        g_ssrc[p] = src[e];
    }
}

// ---------------- conv1 projections (in=3) ----------------
// Q = x@Wsrc + posproj ; eq = exp(-Q) ; ev = eq * (x@Wval - posproj) ; Dc = posproj + b
__global__ void k_proj3(const float* __restrict__ x, const float* __restrict__ pos,
                        const float* __restrict__ Wsrc, const float* __restrict__ Wval,
                        const float* __restrict__ Wpos, const float* __restrict__ bpos) {
    int ty = threadIdx.y, lane = threadIdx.x;
    int node = blockIdx.x * 8 + ty;
    if (node >= NN) return;
    int c = 2 * lane;
    float x0 = x[node * 3 + 0], x1 = x[node * 3 + 1], x2 = x[node * 3 + 2];
    float p0 = pos[node * 3 + 0], p1 = pos[node * 3 + 1], p2 = pos[node * 3 + 2];

    float2 aS = make_float2(0.f, 0.f), aV = aS, pp = aS;
    {
        float2 w;
        w = *(const float2*)&Wsrc[0 * HH + c]; aS.x += x0 * w.x; aS.y += x0 * w.y;
        w = *(const float2*)&Wsrc[1 * HH + c]; aS.x += x1 * w.x; aS.y += x1 * w.y;
        w = *(const float2*)&Wsrc[2 * HH + c]; aS.x += x2 * w.x; aS.y += x2 * w.y;
        w = *(const float2*)&Wval[0 * HH + c]; aV.x += x0 * w.x; aV.y += x0 * w.y;
        w = *(const float2*)&Wval[1 * HH + c]; aV.x += x1 * w.x; aV.y += x1 * w.y;
        w = *(const float2*)&Wval[2 * HH + c]; aV.x += x2 * w.x; aV.y += x2 * w.y;
        w = *(const float2*)&Wpos[0 * HH + c]; pp.x += p0 * w.x; pp.y += p0 * w.y;
        w = *(const float2*)&Wpos[1 * HH + c]; pp.x += p1 * w.x; pp.y += p1 * w.y;
        w = *(const float2*)&Wpos[2 * HH + c]; pp.x += p2 * w.x; pp.y += p2 * w.y;
    }
    float2 b = *(const float2*)&bpos[c];
    float eq0 = __expf(-(aS.x + pp.x));
    float eq1 = __expf(-(aS.y + pp.y));
    float ev0 = eq0 * (aV.x - pp.x);
    float ev1 = eq1 * (aV.y - pp.y);
    g_T [node * 32 + lane] = make_float4(eq0, eq1, ev0, ev1);
    g_Dc[node * 32 + lane] = make_float2(pp.x + b.x, pp.y + b.y);
}

// ---------------- conv2 projections (in=H), 4 nodes per thread ----------------
__global__ void k_proj64(const float* __restrict__ pos,
                         const float* __restrict__ Wsrc, const float* __restrict__ Wval,
                         const float* __restrict__ Wpos, const float* __restrict__ bpos) {
    __shared__ float shx[32][HH];    // 32 nodes' features
    int lane = threadIdx.x, ty = threadIdx.y;
    int tid = ty * 32 + lane;
    int nodeBase = blockIdx.x * 32;

    // cooperative load of 32x64 feature tile (float2-coalesced)
    for (int i = tid; i < 32 * (HH / 2); i += 256) {
        int n = i / (HH / 2), k2 = i % (HH / 2);
        int node = nodeBase + n;
        float2 v = (node < NN) ? *(const float2*)&g_h[node * HH + 2 * k2]
                               : make_float2(0.f, 0.f);
        *(float2*)&shx[n][2 * k2] = v;
    }
    __syncthreads();

    int c = 2 * lane;
    int n0 = ty * 4;   // local node base for this thread (4 nodes)
    ull aS[4], aV[4];
#pragma unroll
    for (int j = 0; j < 4; j++) { aS[j] = 0ull; aV[j] = 0ull; }

#pragma unroll 8
    for (int k = 0; k < HH; k++) {
        ull ws = *(const ull*)&Wsrc[k * HH + c];
        ull wv = *(const ull*)&Wval[k * HH + c];
#pragma unroll
        for (int j = 0; j < 4; j++) {
            float xk = shx[n0 + j][k];
            ull xp = PK(xk, xk);
            aS[j] = FMA2(xp, ws, aS[j]);
            aV[j] = FMA2(xp, wv, aV[j]);
        }
    }

    float2 b = *(const float2*)&bpos[c];
    float2 wp0 = *(const float2*)&Wpos[0 * HH + c];
    float2 wp1 = *(const float2*)&Wpos[1 * HH + c];
    float2 wp2 = *(const float2*)&Wpos[2 * HH + c];

#pragma unroll
    for (int j = 0; j < 4; j++) {
        int node = nodeBase + n0 + j;
        if (node >= NN) break;
        float p0 = pos[node * 3 + 0], p1 = pos[node * 3 + 1], p2 = pos[node * 3 + 2];
        float ppx = p0 * wp0.x + p1 * wp1.x + p2 * wp2.x;
        float ppy = p0 * wp0.y + p1 * wp1.y + p2 * wp2.y;
        float2 s = *(float2*)&aS[j];
        float2 v = *(float2*)&aV[j];
        float eq0 = __expf(-(s.x + ppx));
        float eq1 = __expf(-(s.y + ppy));
        float ev0 = eq0 * (v.x - ppx);
        float ev1 = eq1 * (v.y - ppy);
        g_T [node * 32 + lane] = make_float4(eq0, eq1, ev0, ev1);
        g_Dc[node * 32 + lane] = make_float2(ppx + b.x, ppy + b.y);
    }
}

// ---------------- edge aggregation: one warp per dst node ----------------
// out[i] = relu( (sum_e ev[src]) / (sum_e eq[src]) + Dc[i] ),  0 if deg==0
__global__ void k_edge(float* __restrict__ out) {
    int w = (blockIdx.x * blockDim.x + threadIdx.x) >> 5;
    int lane = threadIdx.x & 31;
    if (w >= NN) return;
    int beg = g_rowptr[w], end = g_rowptr[w + 1];

    ull s = 0ull, a = 0ull;
    int e = beg;
    for (; e + 4 <= end; e += 4) {
        int i0 = __ldg(&g_ssrc[e + 0]);
        int i1 = __ldg(&g_ssrc[e + 1]);
        int i2 = __ldg(&g_ssrc[e + 2]);
        int i3 = __ldg(&g_ssrc[e + 3]);
        float4 t0 = __ldg(&g_T[i0 * 32 + lane]);
        float4 t1 = __ldg(&g_T[i1 * 32 + lane]);
        float4 t2 = __ldg(&g_T[i2 * 32 + lane]);
        float4 t3 = __ldg(&g_T[i3 * 32 + lane]);
        s = ADD2(s, PK(t0.x, t0.y)); a = ADD2(a, PK(t0.z, t0.w));
        s = ADD2(s, PK(t1.x, t1.y)); a = ADD2(a, PK(t1.z, t1.w));
        s = ADD2(s, PK(t2.x, t2.y)); a = ADD2(a, PK(t2.z, t2.w));
        s = ADD2(s, PK(t3.x, t3.y)); a = ADD2(a, PK(t3.z, t3.w));
    }
    for (; e < end; e++) {
        int i0 = __ldg(&g_ssrc[e]);
        float4 t0 = __ldg(&g_T[i0 * 32 + lane]);
        s = ADD2(s, PK(t0.x, t0.y)); a = ADD2(a, PK(t0.z, t0.w));
    }

    float2 r;
    if (end > beg) {
        float2 sf = *(float2*)&s;
        float2 af = *(float2*)&a;
        float2 dc = g_Dc[w * 32 + lane];
        r.x = fmaxf(af.x / sf.x + dc.x, 0.f);
        r.y = fmaxf(af.y / sf.y + dc.y, 0.f);
    } else {
        r = make_float2(0.f, 0.f);
    }
    *(float2*)&out[w * HH + 2 * lane] = r;
}

// ---------------- MLP head: one warp per node ----------------
__global__ void k_head(const float* __restrict__ Wfc1, const float* __restrict__ bfc1,
                       const float* __restrict__ Wfc2, const float* __restrict__ bfc2,
                       float* __restrict__ out) {
    int w = (blockIdx.x * blockDim.x + threadIdx.x) >> 5;
    int lane = threadIdx.x & 31;
    if (w >= NN) return;
    float acc = bfc1[lane];
    const float* hr = &g_h[w * HH];
#pragma unroll 8
    for (int k = 0; k < HH; k++) acc += hr[k] * Wfc1[k * 32 + lane];
    acc = fmaxf(acc, 0.f);
    float y = acc * Wfc2[lane];
#pragma unroll
    for (int off = 16; off; off >>= 1) y += __shfl_xor_sync(0xffffffffu, y, off);
    if (lane == 0) out[w] = y + bfc2[0];
}

extern "C" void kernel_launch(void* const* d_in, const int* in_sizes, int n_in,
                              void* d_out, int out_size) {
    const float* x    = (const float*)d_in[0];
    const float* pos  = (const float*)d_in[1];
    const int*   ei   = (const int*)d_in[2];
    // d_in[3] = batch (unused)
    const float* W1s  = (const float*)d_in[4];
    // d_in[5] = W1_dst (unused: cancels in segment softmax)
    const float* W1v  = (const float*)d_in[6];
    const float* W1p  = (const float*)d_in[7];
    const float* b1p  = (const float*)d_in[8];
    const float* W2s  = (const float*)d_in[9];
    // d_in[10] = W2_dst (unused)
    const float* W2v  = (const float*)d_in[11];
    const float* W2p  = (const float*)d_in[12];
    const float* b2p  = (const float*)d_in[13];
    const float* Wf1  = (const float*)d_in[14];
    const float* bf1  = (const float*)d_in[15];
    const float* Wf2  = (const float*)d_in[16];
    const float* bf2  = (const float*)d_in[17];
    float* out = (float*)d_out;

    const int* src = ei;
    const int* dst = ei + EE;

    void* degPtr; cudaGetSymbolAddress(&degPtr, g_deg);
    float* hdev;  cudaGetSymbolAddress((void**)&hdev, g_h);

    int edgeGrid = (EE + 255) / 256;
    int nodeWarpGrid = (NN * 32 + 255) / 256;

    // CSR build
    cudaMemsetAsync(degPtr, 0, NN * sizeof(int));
    k_hist<<<edgeGrid, 256>>>(dst);
    k_scan<<<1, 1024>>>();
    k_scatter<<<edgeGrid, 256>>>(src, dst);

    // conv1
    k_proj3<<<(NN + 7) / 8, dim3(32, 8)>>>(x, pos, W1s, W1v, W1p, b1p);
    k_edge<<<nodeWarpGrid, 256>>>(hdev);

    // conv2
    k_proj64<<<(NN + 31) / 32, dim3(32, 8)>>>(pos, W2s, W2v, W2p, b2p);
    k_edge<<<nodeWarpGrid, 256>>>(hdev);

    // MLP head
    k_head<<<nodeWarpGrid, 256>>>(Wf1, bf1, Wf2, bf2, out);
}

// round 3
// speedup vs baseline: 1.4178x; 1.0981x over previous
#include <cuda_runtime.h>
#include <cuda_fp16.h>
#include <math.h>

#define NN 50000
#define EE 800000
#define HH 64
#define TSCALE 0.015625f   // 2^-6 global scale on (eq, ev); cancels in softmax ratio

// ---- scratch (device globals) ----
__device__ uint2  g_T [NN * 32];   // per node/lane: (half2 eq*S, half2 ev*S)
__device__ float2 g_Dc[NN * 32];   // per node/lane: posproj + b (2 channels)
__device__ float  g_h [NN * HH];   // conv output / next-layer input
__device__ int    g_deg[NN];
__device__ int    g_rowptr[NN + 1];
__device__ int    g_wp[NN];
__device__ int    g_ssrc[EE];

// ---- packed f32x2 helpers ----
typedef unsigned long long ull;
__device__ __forceinline__ ull PK(float x, float y) {
    float2 f = make_float2(x, y);
    return *(ull*)&f;
}
__device__ __forceinline__ ull ADD2(ull a, ull b) {
    ull r; asm("add.rn.f32x2 %0, %1, %2;" : "=l"(r) : "l"(a), "l"(b)); return r;
}
__device__ __forceinline__ ull FMA2(ull a, ull b, ull c) {
    ull r; asm("fma.rn.f32x2 %0, %1, %2, %3;" : "=l"(r) : "l"(a), "l"(b), "l"(c)); return r;
}

// ---------------- CSR build ----------------
__global__ void k_hist(const int4* __restrict__ dst4) {
    int i = blockIdx.x * blockDim.x + threadIdx.x;
    if (i < EE / 4) {
        int4 d = dst4[i];
        atomicAdd(&g_deg[d.x], 1);
        atomicAdd(&g_deg[d.y], 1);
        atomicAdd(&g_deg[d.z], 1);
        atomicAdd(&g_deg[d.w], 1);
    }
}

__global__ void k_scan() {
    const int T = 1024;
    const int ITEMS = (NN + T - 1) / T;
    __shared__ int sh[T];
    int t = threadIdx.x;
    int base = t * ITEMS;
    int sum = 0;
    for (int j = 0; j < ITEMS; j++) {
        int i = base + j;
        if (i < NN) sum += g_deg[i];
    }
    sh[t] = sum;
    __syncthreads();
    for (int d = 1; d < T; d <<= 1) {
        int v = (t >= d) ? sh[t - d] : 0;
        __syncthreads();
        sh[t] += v;
        __syncthreads();
    }
    int run = sh[t] - sum;
    for (int j = 0; j < ITEMS; j++) {
        int i = base + j;
        if (i < NN) {
            g_rowptr[i] = run;
            g_wp[i] = run;
            run += g_deg[i];
        }
    }
    if (t == 0) g_rowptr[NN] = EE;
}

__global__ void k_scatter(const int4* __restrict__ src4, const int4* __restrict__ dst4) {
    int i = blockIdx.x * blockDim.x + threadIdx.x;
    if (i < EE / 4) {
        int4 s = src4[i];
        int4 d = dst4[i];
        g_ssrc[atomicAdd(&g_wp[d.x], 1)] = s.x;
        g_ssrc[atomicAdd(&g_wp[d.y], 1)] = s.y;
        g_ssrc[atomicAdd(&g_wp[d.z], 1)] = s.z;
        g_ssrc[atomicAdd(&g_wp[d.w], 1)] = s.w;
    }
}

// ---------------- fp16 table store helper ----------------
__device__ __forceinline__ void store_T(int node, int lane,
                                        float eq0, float eq1, float ev0, float ev1) {
    uint2 u;
    half2 heq = __floats2half2_rn(eq0 * TSCALE, eq1 * TSCALE);
    half2 hev = __floats2half2_rn(ev0 * TSCALE, ev1 * TSCALE);
    *(half2*)&u.x = heq;
    *(half2*)&u.y = hev;
    g_T[node * 32 + lane] = u;
}

// ---------------- conv1 projections (in=3): 4 nodes/warp, weights in regs ----
__global__ void k_proj3(const float* __restrict__ x, const float* __restrict__ pos,
                        const float* __restrict__ Wsrc, const float* __restrict__ Wval,
                        const float* __restrict__ Wpos, const float* __restrict__ bpos) {
    int lane = threadIdx.x & 31;
    int wid = threadIdx.x >> 5;
    int base = (blockIdx.x * 8 + wid) * 4;
    int c = 2 * lane;

    float2 ws0 = *(const float2*)&Wsrc[0 * HH + c];
    float2 ws1 = *(const float2*)&Wsrc[1 * HH + c];
    float2 ws2 = *(const float2*)&Wsrc[2 * HH + c];
    float2 wv0 = *(const float2*)&Wval[0 * HH + c];
    float2 wv1 = *(const float2*)&Wval[1 * HH + c];
    float2 wv2 = *(const float2*)&Wval[2 * HH + c];
    float2 wp0 = *(const float2*)&Wpos[0 * HH + c];
    float2 wp1 = *(const float2*)&Wpos[1 * HH + c];
    float2 wp2 = *(const float2*)&Wpos[2 * HH + c];
    float2 b   = *(const float2*)&bpos[c];

#pragma unroll
    for (int j = 0; j < 4; j++) {
        int node = base + j;
        if (node >= NN) break;
        float x0 = __ldg(&x[node * 3 + 0]);
        float x1 = __ldg(&x[node * 3 + 1]);
        float x2 = __ldg(&x[node * 3 + 2]);
        float p0 = __ldg(&pos[node * 3 + 0]);
        float p1 = __ldg(&pos[node * 3 + 1]);
        float p2 = __ldg(&pos[node * 3 + 2]);

        float qx = x0 * ws0.x + x1 * ws1.x + x2 * ws2.x;
        float qy = x0 * ws0.y + x1 * ws1.y + x2 * ws2.y;
        float vx = x0 * wv0.x + x1 * wv1.x + x2 * wv2.x;
        float vy = x0 * wv0.y + x1 * wv1.y + x2 * wv2.y;
        float ppx = p0 * wp0.x + p1 * wp1.x + p2 * wp2.x;
        float ppy = p0 * wp0.y + p1 * wp1.y + p2 * wp2.y;

        float eq0 = __expf(-(qx + ppx));
        float eq1 = __expf(-(qy + ppy));
        store_T(node, lane, eq0, eq1, eq0 * (vx - ppx), eq1 * (vy - ppy));
        g_Dc[node * 32 + lane] = make_float2(ppx + b.x, ppy + b.y);
    }
}

// ---------------- conv2 projections (in=H), 4 nodes per thread ----------------
__global__ void k_proj64(const float* __restrict__ pos,
                         const float* __restrict__ Wsrc, const float* __restrict__ Wval,
                         const float* __restrict__ Wpos, const float* __restrict__ bpos) {
    __shared__ float shx[32][HH];
    int lane = threadIdx.x, ty = threadIdx.y;
    int tid = ty * 32 + lane;
    int nodeBase = blockIdx.x * 32;

    for (int i = tid; i < 32 * (HH / 2); i += 256) {
        int n = i / (HH / 2), k2 = i % (HH / 2);
        int node = nodeBase + n;
        float2 v = (node < NN) ? *(const float2*)&g_h[node * HH + 2 * k2]
                               : make_float2(0.f, 0.f);
        *(float2*)&shx[n][2 * k2] = v;
    }
    __syncthreads();

    int c = 2 * lane;
    int n0 = ty * 4;
    ull aS[4], aV[4];
#pragma unroll
    for (int j = 0; j < 4; j++) { aS[j] = 0ull; aV[j] = 0ull; }

#pragma unroll 8
    for (int k = 0; k < HH; k++) {
        ull ws = *(const ull*)&Wsrc[k * HH + c];
        ull wv = *(const ull*)&Wval[k * HH + c];
#pragma unroll
        for (int j = 0; j < 4; j++) {
            float xk = shx[n0 + j][k];
            ull xp = PK(xk, xk);
            aS[j] = FMA2(xp, ws, aS[j]);
            aV[j] = FMA2(xp, wv, aV[j]);
        }
    }

    float2 b   = *(const float2*)&bpos[c];
    float2 wp0 = *(const float2*)&Wpos[0 * HH + c];
    float2 wp1 = *(const float2*)&Wpos[1 * HH + c];
    float2 wp2 = *(const float2*)&Wpos[2 * HH + c];

#pragma unroll
    for (int j = 0; j < 4; j++) {
        int node = nodeBase + n0 + j;
        if (node >= NN) break;
        float p0 = pos[node * 3 + 0], p1 = pos[node * 3 + 1], p2 = pos[node * 3 + 2];
        float ppx = p0 * wp0.x + p1 * wp1.x + p2 * wp2.x;
        float ppy = p0 * wp0.y + p1 * wp1.y + p2 * wp2.y;
        float2 s = *(float2*)&aS[j];
        float2 v = *(float2*)&aV[j];
        float eq0 = __expf(-(s.x + ppx));
        float eq1 = __expf(-(s.y + ppy));
        store_T(node, lane, eq0, eq1, eq0 * (v.x - ppx), eq1 * (v.y - ppy));
        g_Dc[node * 32 + lane] = make_float2(ppx + b.x, ppy + b.y);
    }
}

// ---------------- edge aggregation: one warp per dst node ----------------
__device__ __forceinline__ void acc_edge(int sn, int lane, ull& s, ull& a) {
    uint2 t = __ldg(&g_T[sn * 32 + lane]);
    float2 eq = __half22float2(*(const half2*)&t.x);
    float2 ev = __half22float2(*(const half2*)&t.y);
    s = ADD2(s, PK(eq.x, eq.y));
    a = ADD2(a, PK(ev.x, ev.y));
}

__global__ void k_edge(float* __restrict__ out) {
    int w = (blockIdx.x * blockDim.x + threadIdx.x) >> 5;
    int lane = threadIdx.x & 31;
    if (w >= NN) return;
    int beg = g_rowptr[w], end = g_rowptr[w + 1];

    ull s = 0ull, a = 0ull;
    int e = beg;
    for (; e + 4 <= end; e += 4) {
        int i0 = __ldg(&g_ssrc[e + 0]);
        int i1 = __ldg(&g_ssrc[e + 1]);
        int i2 = __ldg(&g_ssrc[e + 2]);
        int i3 = __ldg(&g_ssrc[e + 3]);
        acc_edge(i0, lane, s, a);
        acc_edge(i1, lane, s, a);
        acc_edge(i2, lane, s, a);
        acc_edge(i3, lane, s, a);
    }
    for (; e < end; e++) {
        int i0 = __ldg(&g_ssrc[e]);
        acc_edge(i0, lane, s, a);
    }

    float2 r;
    if (end > beg) {
        float2 sf = *(float2*)&s;
        float2 af = *(float2*)&a;
        float2 dc = g_Dc[w * 32 + lane];
        r.x = fmaxf(af.x / (sf.x + 1e-12f) + dc.x, 0.f);
        r.y = fmaxf(af.y / (sf.y + 1e-12f) + dc.y, 0.f);
    } else {
        r = make_float2(0.f, 0.f);
    }
    *(float2*)&out[w * HH + 2 * lane] = r;
}

// ---------------- MLP head: shared-transposed W, 8 nodes/warp ----------------
__global__ void k_head(const float* __restrict__ Wfc1, const float* __restrict__ bfc1,
                       const float* __restrict__ Wfc2, const float* __restrict__ bfc2,
                       float* __restrict__ out) {
    __shared__ float2 sW[32 * 32];   // sW[q*32+c] = (W[2q][c], W[2q+1][c])
    __shared__ float sb1[32], sW2[32];
    int tid = threadIdx.x;
    for (int i = tid; i < 1024; i += 256) {
        int q = i >> 5, cc = i & 31;
        sW[i] = make_float2(Wfc1[(2 * q) * 32 + cc], Wfc1[(2 * q + 1) * 32 + cc]);
    }
    if (tid < 32) { sb1[tid] = bfc1[tid]; sW2[tid] = Wfc2[tid]; }
    __syncthreads();

    int lane = tid & 31, wid = tid >> 5;
    int base = (blockIdx.x * 8 + wid) * 8;
    float b2 = bfc2[0];
#pragma unroll
    for (int j = 0; j < 8; j++) {
        int w = base + j;
        if (w >= NN) break;
        float2 hv = *(const float2*)&g_h[w * HH + 2 * lane];
        float acc = sb1[lane];
#pragma unroll
        for (int q = 0; q < 32; q++) {
            float hx = __shfl_sync(0xffffffffu, hv.x, q);
            float hy = __shfl_sync(0xffffffffu, hv.y, q);
            float2 wv = sW[q * 32 + lane];
            acc = fmaf(hx, wv.x, fmaf(hy, wv.y, acc));
        }
        acc = fmaxf(acc, 0.f);
        float y = acc * sW2[lane];
#pragma unroll
        for (int off = 16; off; off >>= 1) y += __shfl_xor_sync(0xffffffffu, y, off);
        if (lane == 0) out[w] = y + b2;
    }
}

extern "C" void kernel_launch(void* const* d_in, const int* in_sizes, int n_in,
                              void* d_out, int out_size) {
    const float* x    = (const float*)d_in[0];
    const float* pos  = (const float*)d_in[1];
    const int*   ei   = (const int*)d_in[2];
    // d_in[3] = batch (unused)
    const float* W1s  = (const float*)d_in[4];
    // d_in[5] = W1_dst (unused: cancels in segment softmax)
    const float* W1v  = (const float*)d_in[6];
    const float* W1p  = (const float*)d_in[7];
    const float* b1p  = (const float*)d_in[8];
    const float* W2s  = (const float*)d_in[9];
    // d_in[10] = W2_dst (unused)
    const float* W2v  = (const float*)d_in[11];
    const float* W2p  = (const float*)d_in[12];
    const float* b2p  = (const float*)d_in[13];
    const float* Wf1  = (const float*)d_in[14];
    const float* bf1  = (const float*)d_in[15];
    const float* Wf2  = (const float*)d_in[16];
    const float* bf2  = (const float*)d_in[17];
    float* out = (float*)d_out;

    const int4* src4 = (const int4*)ei;
    const int4* dst4 = (const int4*)(ei + EE);

    void* degPtr; cudaGetSymbolAddress(&degPtr, g_deg);
    float* hdev;  cudaGetSymbolAddress((void**)&hdev, g_h);

    int vecGrid = (EE / 4 + 255) / 256;        // 782
    int nodeWarpGrid = (NN * 32 + 255) / 256;  // 6250

    // CSR build
    cudaMemsetAsync(degPtr, 0, NN * sizeof(int));
    k_hist<<<vecGrid, 256>>>(dst4);
    k_scan<<<1, 1024>>>();
    k_scatter<<<vecGrid, 256>>>(src4, dst4);

    // conv1
    k_proj3<<<(NN + 31) / 32, 256>>>(x, pos, W1s, W1v, W1p, b1p);
    k_edge<<<nodeWarpGrid, 256>>>(hdev);

    // conv2
    k_proj64<<<(NN + 31) / 32, dim3(32, 8)>>>(pos, W2s, W2v, W2p, b2p);
    k_edge<<<nodeWarpGrid, 256>>>(hdev);

    // MLP head
    k_head<<<(NN + 63) / 64, 256>>>(Wf1, bf1, Wf2, bf2, out);
}

// round 4
// speedup vs baseline: 1.5672x; 1.1054x over previous
#include <cuda_runtime.h>
#include <cuda_fp16.h>
#include <math.h>

#define NN 50000
#define EE 800000
#define HH 64
#define TSCALE 0.015625f   // 2^-6 global scale on (eq, ev); cancels in softmax ratio

#define SCAN_CHUNK 1024
#define SCAN_NB ((NN + SCAN_CHUNK - 1) / SCAN_CHUNK)   // 49

// ---- scratch (device globals) ----
__device__ uint2  g_T [NN * 32];   // per node/lane: (half2 eq*S, half2 ev*S)
__device__ float2 g_Dc[NN * 32];   // per node/lane: posproj + b (2 channels)
__device__ float  g_h [NN * HH];   // conv1 output (conv2 input)
__device__ int    g_deg[NN];
__device__ int    g_rowptr[NN + 1];
__device__ int    g_wp[NN];
__device__ int    g_ssrc[EE];
__device__ int    g_bsum[SCAN_NB];
__device__ int    g_boff[SCAN_NB];

// ---- packed f32x2 helpers ----
typedef unsigned long long ull;
__device__ __forceinline__ ull PK(float x, float y) {
    float2 f = make_float2(x, y);
    return *(ull*)&f;
}
__device__ __forceinline__ ull ADD2(ull a, ull b) {
    ull r; asm("add.rn.f32x2 %0, %1, %2;" : "=l"(r) : "l"(a), "l"(b)); return r;
}
__device__ __forceinline__ ull FMA2(ull a, ull b, ull c) {
    ull r; asm("fma.rn.f32x2 %0, %1, %2, %3;" : "=l"(r) : "l"(a), "l"(b), "l"(c)); return r;
}

// ---------------- CSR build ----------------
__global__ void k_hist(const int4* __restrict__ dst4) {
    int i = blockIdx.x * blockDim.x + threadIdx.x;
    if (i < EE / 4) {
        int4 d = dst4[i];
        atomicAdd(&g_deg[d.x], 1);
        atomicAdd(&g_deg[d.y], 1);
        atomicAdd(&g_deg[d.z], 1);
        atomicAdd(&g_deg[d.w], 1);
    }
}

// Phase A: per-block total of 1024 deg values (int4-coalesced)
__global__ void k_scanA() {
    int t = threadIdx.x, b = blockIdx.x;
    int gbase = b * SCAN_CHUNK + t * 4;
    int tsum = 0;
    if (gbase < NN) {
        int4 v = *(const int4*)&g_deg[gbase];
        tsum = v.x + v.y + v.z + v.w;
    }
#pragma unroll
    for (int off = 16; off; off >>= 1) tsum += __shfl_xor_sync(0xffffffffu, tsum, off);
    __shared__ int sw[8];
    int lane = t & 31, wid = t >> 5;
    if (lane == 0) sw[wid] = tsum;
    __syncthreads();
    if (t == 0) {
        int s = 0;
#pragma unroll
        for (int j = 0; j < 8; j++) s += sw[j];
        g_bsum[b] = s;
    }
}

// Phase B: one warp scans 49 block sums -> exclusive offsets; also rowptr[NN]=EE
__global__ void k_scanB() {
    int lane = threadIdx.x;
    int v0 = (lane < SCAN_NB) ? g_bsum[lane] : 0;
    int v1 = (lane + 32 < SCAN_NB) ? g_bsum[lane + 32] : 0;
    int i0 = v0, i1 = v1;
#pragma unroll
    for (int d = 1; d < 32; d <<= 1) {
        int a = __shfl_up_sync(0xffffffffu, i0, d);
        int b = __shfl_up_sync(0xffffffffu, i1, d);
        if (lane >= d) { i0 += a; i1 += b; }
    }
    int tot0 = __shfl_sync(0xffffffffu, i0, 31);
    if (lane < SCAN_NB) g_boff[lane] = i0 - v0;
    if (lane + 32 < SCAN_NB) g_boff[lane + 32] = tot0 + i1 - v1;
    if (lane == 0) g_rowptr[NN] = EE;
}

// Phase C: re-scan chunk with global offset, write rowptr & wp (int4)
__global__ void k_scanC() {
    __shared__ int ssum[256];
    int t = threadIdx.x, b = blockIdx.x;
    int gbase = b * SCAN_CHUNK + t * 4;
    int4 v = make_int4(0, 0, 0, 0);
    if (gbase < NN) v = *(const int4*)&g_deg[gbase];
    int tsum = v.x + v.y + v.z + v.w;
    ssum[t] = tsum;
    __syncthreads();
    for (int d = 1; d < 256; d <<= 1) {
        int a = (t >= d) ? ssum[t - d] : 0;
        __syncthreads();
        ssum[t] += a;
        __syncthreads();
    }
    if (gbase < NN) {
        int base = g_boff[b] + ssum[t] - tsum;
        int4 r;
        r.x = base;
        r.y = base + v.x;
        r.z = r.y + v.y;
        r.w = r.z + v.z;
        *(int4*)&g_rowptr[gbase] = r;
        *(int4*)&g_wp[gbase] = r;
    }
}

__global__ void k_scatter(const int4* __restrict__ src4, const int4* __restrict__ dst4) {
    int i = blockIdx.x * blockDim.x + threadIdx.x;
    if (i < EE / 4) {
        int4 s = src4[i];
        int4 d = dst4[i];
        g_ssrc[atomicAdd(&g_wp[d.x], 1)] = s.x;
        g_ssrc[atomicAdd(&g_wp[d.y], 1)] = s.y;
        g_ssrc[atomicAdd(&g_wp[d.z], 1)] = s.z;
        g_ssrc[atomicAdd(&g_wp[d.w], 1)] = s.w;
    }
}

// ---------------- fp16 table store ----------------
__device__ __forceinline__ void store_T(int node, int lane,
                                        float eq0, float eq1, float ev0, float ev1) {
    uint2 u;
    half2 heq = __floats2half2_rn(eq0 * TSCALE, eq1 * TSCALE);
    half2 hev = __floats2half2_rn(ev0 * TSCALE, ev1 * TSCALE);
    *(half2*)&u.x = heq;
    *(half2*)&u.y = hev;
    g_T[node * 32 + lane] = u;
}

// ---------------- conv1 projections (in=3) ----------------
__global__ void k_proj3(const float* __restrict__ x, const float* __restrict__ pos,
                        const float* __restrict__ Wsrc, const float* __restrict__ Wval,
                        const float* __restrict__ Wpos, const float* __restrict__ bpos) {
    int lane = threadIdx.x & 31;
    int wid = threadIdx.x >> 5;
    int base = (blockIdx.x * 8 + wid) * 4;
    int c = 2 * lane;

    float2 ws0 = *(const float2*)&Wsrc[0 * HH + c];
    float2 ws1 = *(const float2*)&Wsrc[1 * HH + c];
    float2 ws2 = *(const float2*)&Wsrc[2 * HH + c];
    float2 wv0 = *(const float2*)&Wval[0 * HH + c];
    float2 wv1 = *(const float2*)&Wval[1 * HH + c];
    float2 wv2 = *(const float2*)&Wval[2 * HH + c];
    float2 wp0 = *(const float2*)&Wpos[0 * HH + c];
    float2 wp1 = *(const float2*)&Wpos[1 * HH + c];
    float2 wp2 = *(const float2*)&Wpos[2 * HH + c];
    float2 b   = *(const float2*)&bpos[c];

#pragma unroll
    for (int j = 0; j < 4; j++) {
        int node = base + j;
        if (node >= NN) break;
        float x0 = __ldg(&x[node * 3 + 0]);
        float x1 = __ldg(&x[node * 3 + 1]);
        float x2 = __ldg(&x[node * 3 + 2]);
        float p0 = __ldg(&pos[node * 3 + 0]);
        float p1 = __ldg(&pos[node * 3 + 1]);
        float p2 = __ldg(&pos[node * 3 + 2]);

        float qx = x0 * ws0.x + x1 * ws1.x + x2 * ws2.x;
        float qy = x0 * ws0.y + x1 * ws1.y + x2 * ws2.y;
        float vx = x0 * wv0.x + x1 * wv1.x + x2 * wv2.x;
        float vy = x0 * wv0.y + x1 * wv1.y + x2 * wv2.y;
        float ppx = p0 * wp0.x + p1 * wp1.x + p2 * wp2.x;
        float ppy = p0 * wp0.y + p1 * wp1.y + p2 * wp2.y;

        float eq0 = __expf(-(qx + ppx));
        float eq1 = __expf(-(qy + ppy));
        store_T(node, lane, eq0, eq1, eq0 * (vx - ppx), eq1 * (vy - ppy));
        g_Dc[node * 32 + lane] = make_float2(ppx + b.x, ppy + b.y);
    }
}

// ---------------- conv2 projections (in=H): shared weights, 4 nodes/thread ----
__global__ void k_proj64(const float* __restrict__ pos,
                         const float* __restrict__ Wsrc, const float* __restrict__ Wval,
                         const float* __restrict__ Wpos, const float* __restrict__ bpos) {
    __shared__ float shx[32][HH];       // 8 KB
    __shared__ ull sWs[HH * 32];        // 16 KB (Wsrc as lane-pairs)
    __shared__ ull sWv[HH * 32];        // 16 KB
    int lane = threadIdx.x, ty = threadIdx.y;
    int tid = ty * 32 + lane;
    int nodeBase = blockIdx.x * 32;

    const ull* Ws8 = (const ull*)Wsrc;
    const ull* Wv8 = (const ull*)Wval;
    for (int i = tid; i < HH * 32; i += 256) {
        sWs[i] = Ws8[i];
        sWv[i] = Wv8[i];
    }
    for (int i = tid; i < 32 * (HH / 2); i += 256) {
        int n = i / (HH / 2), k2 = i % (HH / 2);
        int node = nodeBase + n;
        float2 v = (node < NN) ? *(const float2*)&g_h[node * HH + 2 * k2]
                               : make_float2(0.f, 0.f);
        *(float2*)&shx[n][2 * k2] = v;
    }
    __syncthreads();

    int c = 2 * lane;
    int n0 = ty * 4;
    ull aS[4], aV[4];
#pragma unroll
    for (int j = 0; j < 4; j++) { aS[j] = 0ull; aV[j] = 0ull; }

#pragma unroll 8
    for (int k = 0; k < HH; k++) {
        ull ws = sWs[k * 32 + lane];
        ull wv = sWv[k * 32 + lane];
#pragma unroll
        for (int j = 0; j < 4; j++) {
            float xk = shx[n0 + j][k];
            ull xp = PK(xk, xk);
            aS[j] = FMA2(xp, ws, aS[j]);
            aV[j] = FMA2(xp, wv, aV[j]);
        }
    }

    float2 b   = *(const float2*)&bpos[c];
    float2 wp0 = *(const float2*)&Wpos[0 * HH + c];
    float2 wp1 = *(const float2*)&Wpos[1 * HH + c];
    float2 wp2 = *(const float2*)&Wpos[2 * HH + c];

#pragma unroll
    for (int j = 0; j < 4; j++) {
        int node = nodeBase + n0 + j;
        if (node >= NN) break;
        float p0 = pos[node * 3 + 0], p1 = pos[node * 3 + 1], p2 = pos[node * 3 + 2];
        float ppx = p0 * wp0.x + p1 * wp1.x + p2 * wp2.x;
        float ppy = p0 * wp0.y + p1 * wp1.y + p2 * wp2.y;
        float2 s = *(float2*)&aS[j];
        float2 v = *(float2*)&aV[j];
        float eq0 = __expf(-(s.x + ppx));
        float eq1 = __expf(-(s.y + ppy));
        store_T(node, lane, eq0, eq1, eq0 * (v.x - ppx), eq1 * (v.y - ppy));
        g_Dc[node * 32 + lane] = make_float2(ppx + b.x, ppy + b.y);
    }
}

// ---------------- edge core: accumulate one node's neighborhood ----------------
__device__ __forceinline__ void acc_edge(int sn, int lane, ull& s, ull& a) {
    uint2 t = __ldg(&g_T[sn * 32 + lane]);
    float2 eq = __half22float2(*(const half2*)&t.x);
    float2 ev = __half22float2(*(const half2*)&t.y);
    s = ADD2(s, PK(eq.x, eq.y));
    a = ADD2(a, PK(ev.x, ev.y));
}

__device__ __forceinline__ float2 edge_node(int w, int lane) {
    int beg = g_rowptr[w], end = g_rowptr[w + 1];
    ull s = 0ull, a = 0ull;
    int e = beg;
    for (; e + 8 <= end; e += 8) {
        int i0 = __ldg(&g_ssrc[e + 0]);
        int i1 = __ldg(&g_ssrc[e + 1]);
        int i2 = __ldg(&g_ssrc[e + 2]);
        int i3 = __ldg(&g_ssrc[e + 3]);
        int i4 = __ldg(&g_ssrc[e + 4]);
        int i5 = __ldg(&g_ssrc[e + 5]);
        int i6 = __ldg(&g_ssrc[e + 6]);
        int i7 = __ldg(&g_ssrc[e + 7]);
        acc_edge(i0, lane, s, a); acc_edge(i1, lane, s, a);
        acc_edge(i2, lane, s, a); acc_edge(i3, lane, s, a);
        acc_edge(i4, lane, s, a); acc_edge(i5, lane, s, a);
        acc_edge(i6, lane, s, a); acc_edge(i7, lane, s, a);
    }
    for (; e < end; e++) acc_edge(__ldg(&g_ssrc[e]), lane, s, a);

    float2 r;
    if (end > beg) {
        float2 sf = *(float2*)&s;
        float2 af = *(float2*)&a;
        float2 dc = g_Dc[w * 32 + lane];
        r.x = fmaxf(af.x / (sf.x + 1e-12f) + dc.x, 0.f);
        r.y = fmaxf(af.y / (sf.y + 1e-12f) + dc.y, 0.f);
    } else {
        r = make_float2(0.f, 0.f);
    }
    return r;
}

// conv1 edge pass: write h
__global__ void k_edge(float* __restrict__ out) {
    int w = (blockIdx.x * blockDim.x + threadIdx.x) >> 5;
    int lane = threadIdx.x & 31;
    if (w >= NN) return;
    float2 r = edge_node(w, lane);
    *(float2*)&out[w * HH + 2 * lane] = r;
}

// conv2 edge pass fused with MLP head: out[w] = (relu(h@Wfc1+b1))@Wfc2+b2
__global__ void k_edge_head(const float* __restrict__ Wfc1, const float* __restrict__ bfc1,
                            const float* __restrict__ Wfc2, const float* __restrict__ bfc2,
                            float* __restrict__ out) {
    __shared__ float2 sW[32 * 32];   // sW[q*32+c] = (Wfc1[2q][c], Wfc1[2q+1][c])
    __shared__ float sb1[32], sW2[32];
    int tid = threadIdx.x;
    for (int i = tid; i < 1024; i += 256) {
        int q = i >> 5, cc = i & 31;
        sW[i] = make_float2(Wfc1[(2 * q) * 32 + cc], Wfc1[(2 * q + 1) * 32 + cc]);
    }
    if (tid < 32) { sb1[tid] = bfc1[tid]; sW2[tid] = Wfc2[tid]; }
    __syncthreads();

    int w = (blockIdx.x * blockDim.x + tid) >> 5;
    int lane = tid & 31;
    if (w >= NN) return;
    float2 hv = edge_node(w, lane);    // relu'd conv2 output, channels 2l,2l+1

    float acc = sb1[lane];
#pragma unroll
    for (int q = 0; q < 32; q++) {
        float hx = __shfl_sync(0xffffffffu, hv.x, q);
        float hy = __shfl_sync(0xffffffffu, hv.y, q);
        float2 wv = sW[q * 32 + lane];
        acc = fmaf(hx, wv.x, fmaf(hy, wv.y, acc));
    }
    acc = fmaxf(acc, 0.f);
    float y = acc * sW2[lane];
#pragma unroll
    for (int off = 16; off; off >>= 1) y += __shfl_xor_sync(0xffffffffu, y, off);
    if (lane == 0) out[w] = y + bfc2[0];
}

extern "C" void kernel_launch(void* const* d_in, const int* in_sizes, int n_in,
                              void* d_out, int out_size) {
    const float* x    = (const float*)d_in[0];
    const float* pos  = (const float*)d_in[1];
    const int*   ei   = (const int*)d_in[2];
    const float* W1s  = (const float*)d_in[4];
    const float* W1v  = (const float*)d_in[6];
    const float* W1p  = (const float*)d_in[7];
    const float* b1p  = (const float*)d_in[8];
    const float* W2s  = (const float*)d_in[9];
    const float* W2v  = (const float*)d_in[11];
    const float* W2p  = (const float*)d_in[12];
    const float* b2p  = (const float*)d_in[13];
    const float* Wf1  = (const float*)d_in[14];
    const float* bf1  = (const float*)d_in[15];
    const float* Wf2  = (const float*)d_in[16];
    const float* bf2  = (const float*)d_in[17];
    float* out = (float*)d_out;

    const int4* src4 = (const int4*)ei;
    const int4* dst4 = (const int4*)(ei + EE);

    void* degPtr; cudaGetSymbolAddress(&degPtr, g_deg);
    float* hdev;  cudaGetSymbolAddress((void**)&hdev, g_h);

    int vecGrid = (EE / 4 + 255) / 256;
    int nodeWarpGrid = (NN * 32 + 255) / 256;

    // fork: CSR build on side stream, proj3 on main stream (capture-safe pattern)
    cudaStream_t s2;
    cudaStreamCreate(&s2);
    cudaEvent_t evF, evJ;
    cudaEventCreateWithFlags(&evF, cudaEventDisableTiming);
    cudaEventCreateWithFlags(&evJ, cudaEventDisableTiming);

    cudaEventRecord(evF, 0);
    cudaStreamWaitEvent(s2, evF, 0);

    // CSR chain (side stream)
    cudaMemsetAsync(degPtr, 0, NN * sizeof(int), s2);
    k_hist<<<vecGrid, 256, 0, s2>>>(dst4);
    k_scanA<<<SCAN_NB, 256, 0, s2>>>();
    k_scanB<<<1, 32, 0, s2>>>();
    k_scanC<<<SCAN_NB, 256, 0, s2>>>();
    k_scatter<<<vecGrid, 256, 0, s2>>>(src4, dst4);
    cudaEventRecord(evJ, s2);

    // conv1 projections (main stream, concurrent with CSR build)
    k_proj3<<<(NN + 31) / 32, 256>>>(x, pos, W1s, W1v, W1p, b1p);

    cudaStreamWaitEvent(0, evJ, 0);

    // conv1 edge pass
    k_edge<<<nodeWarpGrid, 256>>>(hdev);

    // conv2
    k_proj64<<<(NN + 31) / 32, dim3(32, 8)>>>(pos, W2s, W2v, W2p, b2p);
    k_edge_head<<<nodeWarpGrid, 256>>>(Wf1, bf1, Wf2, bf2, out);
}

// round 5
// speedup vs baseline: 1.9250x; 1.2283x over previous
#include <cuda_runtime.h>
#include <cuda_fp16.h>
#include <math.h>

#define NN 50000
#define EE 800000
#define HH 64
#define TSCALE 0.015625f   // 2^-6 global scale on (eq, ev); cancels in softmax ratio

#define SCAN_CHUNK 1024
#define SCAN_NB ((NN + SCAN_CHUNK - 1) / SCAN_CHUNK)   // 49

// ---- scratch (device globals) ----
__device__ uint2  g_T [NN * 32];   // per node/lane: (half2 eq*S, half2 ev*S)
__device__ float2 g_Dc[NN * 32];   // per node/lane: posproj + b (2 channels)
__device__ float  g_h [NN * HH];   // conv1 output (conv2 input)
__device__ int    g_deg[NN];       // zero at start of every launch (self-cleaned)
__device__ int    g_rowptr[NN + 1];
__device__ int    g_rank[EE];
__device__ int    g_ssrc[EE];
__device__ int    g_bsum[SCAN_NB];
__device__ int    g_boff[SCAN_NB];
__device__ int    g_ctr;           // last-block counter (self-resetting)

// ---- packed f32x2 helpers ----
typedef unsigned long long ull;
__device__ __forceinline__ ull PK(float x, float y) {
    float2 f = make_float2(x, y);
    return *(ull*)&f;
}
__device__ __forceinline__ ull ADD2(ull a, ull b) {
    ull r; asm("add.rn.f32x2 %0, %1, %2;" : "=l"(r) : "l"(a), "l"(b)); return r;
}
__device__ __forceinline__ ull FMA2(ull a, ull b, ull c) {
    ull r; asm("fma.rn.f32x2 %0, %1, %2, %3;" : "=l"(r) : "l"(a), "l"(b), "l"(c)); return r;
}

// ---------------- CSR build ----------------
// hist + per-edge rank (returned by atomicAdd) -> scatter needs no atomics
__global__ void k_hist(const int4* __restrict__ dst4) {
    int i = blockIdx.x * blockDim.x + threadIdx.x;
    if (i < EE / 4) {
        int4 d = dst4[i];
        int4 r;
        r.x = atomicAdd(&g_deg[d.x], 1);
        r.y = atomicAdd(&g_deg[d.y], 1);
        r.z = atomicAdd(&g_deg[d.z], 1);
        r.w = atomicAdd(&g_deg[d.w], 1);
        *(int4*)&g_rank[i * 4] = r;
    }
}

// Phase A+B fused: per-block sums; last block scans the 49 sums.
__global__ void k_scanAB() {
    int t = threadIdx.x, b = blockIdx.x;
    int gbase = b * SCAN_CHUNK + t * 4;
    int tsum = 0;
    if (gbase < NN) {
        int4 v = *(const int4*)&g_deg[gbase];
        tsum = v.x + v.y + v.z + v.w;
    }
#pragma unroll
    for (int off = 16; off; off >>= 1) tsum += __shfl_xor_sync(0xffffffffu, tsum, off);
    __shared__ int sw[8];
    __shared__ int isLast;
    int lane = t & 31, wid = t >> 5;
    if (lane == 0) sw[wid] = tsum;
    __syncthreads();
    if (t == 0) {
        int s = 0;
#pragma unroll
        for (int j = 0; j < 8; j++) s += sw[j];
        g_bsum[b] = s;
        __threadfence();
        int done = atomicAdd(&g_ctr, 1);
        isLast = (done == (int)gridDim.x - 1);
        if (isLast) g_ctr = 0;
    }
    __syncthreads();
    if (!isLast) return;
    if (t < 32) {
        __threadfence();
        int v0 = (t < SCAN_NB) ? g_bsum[t] : 0;
        int v1 = (t + 32 < SCAN_NB) ? g_bsum[t + 32] : 0;
        int i0 = v0, i1 = v1;
#pragma unroll
        for (int d = 1; d < 32; d <<= 1) {
            int a = __shfl_up_sync(0xffffffffu, i0, d);
            int b2 = __shfl_up_sync(0xffffffffu, i1, d);
            if (t >= d) { i0 += a; i1 += b2; }
        }
        int tot0 = __shfl_sync(0xffffffffu, i0, 31);
        if (t < SCAN_NB) g_boff[t] = i0 - v0;
        if (t + 32 < SCAN_NB) g_boff[t + 32] = tot0 + i1 - v1;
        if (t == 0) g_rowptr[NN] = EE;
    }
}

// Phase C: shuffle-scan chunk, write rowptr; zero deg for the next launch.
__global__ void k_scanC() {
    int t = threadIdx.x, b = blockIdx.x;
    int gbase = b * SCAN_CHUNK + t * 4;
    int4 v = make_int4(0, 0, 0, 0);
    if (gbase < NN) {
        v = *(const int4*)&g_deg[gbase];
        *(int4*)&g_deg[gbase] = make_int4(0, 0, 0, 0);   // self-clean for next launch
    }
    int tsum = v.x + v.y + v.z + v.w;
    int lane = t & 31, wid = t >> 5;
    int inc = tsum;
#pragma unroll
    for (int d = 1; d < 32; d <<= 1) {
        int a = __shfl_up_sync(0xffffffffu, inc, d);
        if (lane >= d) inc += a;
    }
    __shared__ int swp[8], soff[8];
    if (lane == 31) swp[wid] = inc;
    __syncthreads();
    if (t < 8) {
        int vb = swp[t];
        int ib = vb;
#pragma unroll
        for (int d = 1; d < 8; d <<= 1) {
            int a = __shfl_up_sync(0xffu, ib, d);
            if (t >= d) ib += a;
        }
        soff[t] = ib - vb;
    }
    __syncthreads();
    if (gbase < NN) {
        int base = g_boff[b] + soff[wid] + inc - tsum;
        int4 r;
        r.x = base;
        r.y = base + v.x;
        r.z = r.y + v.y;
        r.w = r.z + v.z;
        *(int4*)&g_rowptr[gbase] = r;
    }
}

// Atomic-free scatter: position = rowptr[dst] + rank
__global__ void k_scatter(const int4* __restrict__ src4, const int4* __restrict__ dst4) {
    int i = blockIdx.x * blockDim.x + threadIdx.x;
    if (i < EE / 4) {
        int4 s = *(const int4*)&src4[i];
        int4 d = *(const int4*)&dst4[i];
        int4 r = *(const int4*)&g_rank[i * 4];
        g_ssrc[__ldg(&g_rowptr[d.x]) + r.x] = s.x;
        g_ssrc[__ldg(&g_rowptr[d.y]) + r.y] = s.y;
        g_ssrc[__ldg(&g_rowptr[d.z]) + r.z] = s.z;
        g_ssrc[__ldg(&g_rowptr[d.w]) + r.w] = s.w;
    }
}

// ---------------- fp16 table store ----------------
__device__ __forceinline__ void store_T(int node, int lane,
                                        float eq0, float eq1, float ev0, float ev1) {
    uint2 u;
    half2 heq = __floats2half2_rn(eq0 * TSCALE, eq1 * TSCALE);
    half2 hev = __floats2half2_rn(ev0 * TSCALE, ev1 * TSCALE);
    *(half2*)&u.x = heq;
    *(half2*)&u.y = hev;
    g_T[node * 32 + lane] = u;
}

// ---------------- conv1 projections (in=3) ----------------
__global__ void k_proj3(const float* __restrict__ x, const float* __restrict__ pos,
                        const float* __restrict__ Wsrc, const float* __restrict__ Wval,
                        const float* __restrict__ Wpos, const float* __restrict__ bpos) {
    int lane = threadIdx.x & 31;
    int wid = threadIdx.x >> 5;
    int base = (blockIdx.x * 8 + wid) * 4;
    int c = 2 * lane;

    float2 ws0 = *(const float2*)&Wsrc[0 * HH + c];
    float2 ws1 = *(const float2*)&Wsrc[1 * HH + c];
    float2 ws2 = *(const float2*)&Wsrc[2 * HH + c];
    float2 wv0 = *(const float2*)&Wval[0 * HH + c];
    float2 wv1 = *(const float2*)&Wval[1 * HH + c];
    float2 wv2 = *(const float2*)&Wval[2 * HH + c];
    float2 wp0 = *(const float2*)&Wpos[0 * HH + c];
    float2 wp1 = *(const float2*)&Wpos[1 * HH + c];
    float2 wp2 = *(const float2*)&Wpos[2 * HH + c];
    float2 b   = *(const float2*)&bpos[c];

#pragma unroll
    for (int j = 0; j < 4; j++) {
        int node = base + j;
        if (node >= NN) break;
        float x0 = __ldg(&x[node * 3 + 0]);
        float x1 = __ldg(&x[node * 3 + 1]);
        float x2 = __ldg(&x[node * 3 + 2]);
        float p0 = __ldg(&pos[node * 3 + 0]);
        float p1 = __ldg(&pos[node * 3 + 1]);
        float p2 = __ldg(&pos[node * 3 + 2]);

        float qx = x0 * ws0.x + x1 * ws1.x + x2 * ws2.x;
        float qy = x0 * ws0.y + x1 * ws1.y + x2 * ws2.y;
        float vx = x0 * wv0.x + x1 * wv1.x + x2 * wv2.x;
        float vy = x0 * wv0.y + x1 * wv1.y + x2 * wv2.y;
        float ppx = p0 * wp0.x + p1 * wp1.x + p2 * wp2.x;
        float ppy = p0 * wp0.y + p1 * wp1.y + p2 * wp2.y;

        float eq0 = __expf(-(qx + ppx));
        float eq1 = __expf(-(qy + ppy));
        store_T(node, lane, eq0, eq1, eq0 * (vx - ppx), eq1 * (vy - ppy));
        g_Dc[node * 32 + lane] = make_float2(ppx + b.x, ppy + b.y);
    }
}

// ---------------- conv2 projections (in=H): shared weights, 4 nodes/thread ----
__global__ void k_proj64(const float* __restrict__ pos,
                         const float* __restrict__ Wsrc, const float* __restrict__ Wval,
                         const float* __restrict__ Wpos, const float* __restrict__ bpos) {
    __shared__ float shx[32][HH];
    __shared__ ull sWs[HH * 32];
    __shared__ ull sWv[HH * 32];
    int lane = threadIdx.x, ty = threadIdx.y;
    int tid = ty * 32 + lane;
    int nodeBase = blockIdx.x * 32;

    const ull* Ws8 = (const ull*)Wsrc;
    const ull* Wv8 = (const ull*)Wval;
    for (int i = tid; i < HH * 32; i += 256) {
        sWs[i] = Ws8[i];
        sWv[i] = Wv8[i];
    }
    for (int i = tid; i < 32 * (HH / 2); i += 256) {
        int n = i / (HH / 2), k2 = i % (HH / 2);
        int node = nodeBase + n;
        float2 v = (node < NN) ? *(const float2*)&g_h[node * HH + 2 * k2]
                               : make_float2(0.f, 0.f);
        *(float2*)&shx[n][2 * k2] = v;
    }
    __syncthreads();

    int c = 2 * lane;
    int n0 = ty * 4;
    ull aS[4], aV[4];
#pragma unroll
    for (int j = 0; j < 4; j++) { aS[j] = 0ull; aV[j] = 0ull; }

#pragma unroll 8
    for (int k = 0; k < HH; k++) {
        ull ws = sWs[k * 32 + lane];
        ull wv = sWv[k * 32 + lane];
#pragma unroll
        for (int j = 0; j < 4; j++) {
            float xk = shx[n0 + j][k];
            ull xp = PK(xk, xk);
            aS[j] = FMA2(xp, ws, aS[j]);
            aV[j] = FMA2(xp, wv, aV[j]);
        }
    }

    float2 b   = *(const float2*)&bpos[c];
    float2 wp0 = *(const float2*)&Wpos[0 * HH + c];
    float2 wp1 = *(const float2*)&Wpos[1 * HH + c];
    float2 wp2 = *(const float2*)&Wpos[2 * HH + c];

#pragma unroll
    for (int j = 0; j < 4; j++) {
        int node = nodeBase + n0 + j;
        if (node >= NN) break;
        float p0 = pos[node * 3 + 0], p1 = pos[node * 3 + 1], p2 = pos[node * 3 + 2];
        float ppx = p0 * wp0.x + p1 * wp1.x + p2 * wp2.x;
        float ppy = p0 * wp0.y + p1 * wp1.y + p2 * wp2.y;
        float2 s = *(float2*)&aS[j];
        float2 v = *(float2*)&aV[j];
        float eq0 = __expf(-(s.x + ppx));
        float eq1 = __expf(-(s.y + ppy));
        store_T(node, lane, eq0, eq1, eq0 * (v.x - ppx), eq1 * (v.y - ppy));
        g_Dc[node * 32 + lane] = make_float2(ppx + b.x, ppy + b.y);
    }
}

// ---------------- edge core ----------------
__device__ __forceinline__ void acc1(const uint2* __restrict__ Tl, int sn, ull& s, ull& a) {
    uint2 t = __ldg(&Tl[sn * 32]);
    float2 eq = __half22float2(*(const half2*)&t.x);
    float2 ev = __half22float2(*(const half2*)&t.y);
    s = ADD2(s, PK(eq.x, eq.y));
    a = ADD2(a, PK(ev.x, ev.y));
}

__device__ __forceinline__ float2 edge_node(int w, int lane) {
    int beg = __ldg(&g_rowptr[w]), end = __ldg(&g_rowptr[w + 1]);
    const uint2* Tl = &g_T[lane];
    ull s0 = 0ull, a0 = 0ull, s1 = 0ull, a1 = 0ull;

    for (int base = beg; base < end; base += 32) {
        int rem = end - base;
        int n = rem < 32 ? rem : 32;
        // one coalesced load of up to 32 neighbor indices
        int idx = __ldg(&g_ssrc[base + (lane < n ? lane : 0)]);
        int j = 0;
        for (; j + 4 <= n; j += 4) {
            int sn0 = __shfl_sync(0xffffffffu, idx, j + 0);
            int sn1 = __shfl_sync(0xffffffffu, idx, j + 1);
            int sn2 = __shfl_sync(0xffffffffu, idx, j + 2);
            int sn3 = __shfl_sync(0xffffffffu, idx, j + 3);
            acc1(Tl, sn0, s0, a0);
            acc1(Tl, sn1, s1, a1);
            acc1(Tl, sn2, s0, a0);
            acc1(Tl, sn3, s1, a1);
        }
        for (; j < n; j++) {
            int sn = __shfl_sync(0xffffffffu, idx, j);
            acc1(Tl, sn, s0, a0);
        }
    }
    ull s = ADD2(s0, s1), a = ADD2(a0, a1);

    float2 r;
    if (end > beg) {
        float2 sf = *(float2*)&s;
        float2 af = *(float2*)&a;
        float2 dc = g_Dc[w * 32 + lane];
        r.x = fmaxf(__fdividef(af.x, sf.x + 1e-12f) + dc.x, 0.f);
        r.y = fmaxf(__fdividef(af.y, sf.y + 1e-12f) + dc.y, 0.f);
    } else {
        r = make_float2(0.f, 0.f);
    }
    return r;
}

// conv1 edge pass
__global__ void k_edge(float* __restrict__ out) {
    int w = (blockIdx.x * blockDim.x + threadIdx.x) >> 5;
    int lane = threadIdx.x & 31;
    if (w >= NN) return;
    float2 r = edge_node(w, lane);
    *(float2*)&out[w * HH + 2 * lane] = r;
}

// conv2 edge pass fused with MLP head
__global__ void k_edge_head(const float* __restrict__ Wfc1, const float* __restrict__ bfc1,
                            const float* __restrict__ Wfc2, const float* __restrict__ bfc2,
                            float* __restrict__ out) {
    __shared__ float2 sW[32 * 32];
    __shared__ float sb1[32], sW2[32];
    int tid = threadIdx.x;
    for (int i = tid; i < 1024; i += 256) {
        int q = i >> 5, cc = i & 31;
        sW[i] = make_float2(Wfc1[(2 * q) * 32 + cc], Wfc1[(2 * q + 1) * 32 + cc]);
    }
    if (tid < 32) { sb1[tid] = bfc1[tid]; sW2[tid] = Wfc2[tid]; }
    __syncthreads();

    int w = (blockIdx.x * blockDim.x + tid) >> 5;
    int lane = tid & 31;
    if (w >= NN) return;
    float2 hv = edge_node(w, lane);

    float acc = sb1[lane];
#pragma unroll
    for (int q = 0; q < 32; q++) {
        float hx = __shfl_sync(0xffffffffu, hv.x, q);
        float hy = __shfl_sync(0xffffffffu, hv.y, q);
        float2 wv = sW[q * 32 + lane];
        acc = fmaf(hx, wv.x, fmaf(hy, wv.y, acc));
    }
    acc = fmaxf(acc, 0.f);
    float y = acc * sW2[lane];
#pragma unroll
    for (int off = 16; off; off >>= 1) y += __shfl_xor_sync(0xffffffffu, y, off);
    if (lane == 0) out[w] = y + bfc2[0];
}

extern "C" void kernel_launch(void* const* d_in, const int* in_sizes, int n_in,
                              void* d_out, int out_size) {
    const float* x    = (const float*)d_in[0];
    const float* pos  = (const float*)d_in[1];
    const int*   ei   = (const int*)d_in[2];
    const float* W1s  = (const float*)d_in[4];
    const float* W1v  = (const float*)d_in[6];
    const float* W1p  = (const float*)d_in[7];
    const float* b1p  = (const float*)d_in[8];
    const float* W2s  = (const float*)d_in[9];
    const float* W2v  = (const float*)d_in[11];
    const float* W2p  = (const float*)d_in[12];
    const float* b2p  = (const float*)d_in[13];
    const float* Wf1  = (const float*)d_in[14];
    const float* bf1  = (const float*)d_in[15];
    const float* Wf2  = (const float*)d_in[16];
    const float* bf2  = (const float*)d_in[17];
    float* out = (float*)d_out;

    const int4* src4 = (const int4*)ei;
    const int4* dst4 = (const int4*)(ei + EE);

    float* hdev;  cudaGetSymbolAddress((void**)&hdev, g_h);

    int vecGrid = (EE / 4 + 255) / 256;
    int nodeWarpGrid = (NN * 32 + 255) / 256;

    cudaStream_t s2;
    cudaStreamCreate(&s2);
    cudaEvent_t evF, evJ;
    cudaEventCreateWithFlags(&evF, cudaEventDisableTiming);
    cudaEventCreateWithFlags(&evJ, cudaEventDisableTiming);

    cudaEventRecord(evF, 0);
    cudaStreamWaitEvent(s2, evF, 0);

    // (1) conv1 projections on main stream (overlaps CSR build)
    k_proj3<<<(NN + 31) / 32, 256>>>(x, pos, W1s, W1v, W1p, b1p);

    // (2-5) CSR chain on side stream (deg starts zero; scanC re-zeroes it)
    k_hist<<<vecGrid, 256, 0, s2>>>(dst4);
    k_scanAB<<<SCAN_NB, 256, 0, s2>>>();
    k_scanC<<<SCAN_NB, 256, 0, s2>>>();
    k_scatter<<<vecGrid, 256, 0, s2>>>(src4, dst4);
    cudaEventRecord(evJ, s2);
    cudaStreamWaitEvent(0, evJ, 0);

    // (6) conv1 edge pass
    k_edge<<<nodeWarpGrid, 256>>>(hdev);

    // (7) conv2 projections, (8) conv2 edge + MLP head
    k_proj64<<<(NN + 31) / 32, dim3(32, 8)>>>(pos, W2s, W2v, W2p, b2p);
    k_edge_head<<<nodeWarpGrid, 256>>>(Wf1, bf1, Wf2, bf2, out);
}